// round 2
// baseline (speedup 1.0000x reference)
#include <cuda_runtime.h>
#include <cuda_bf16.h>
#include <math.h>

// ---------------- static scratch (no allocations allowed) ----------------
#define MAXN 100000
#define MAXE 1600000
#define NGRAPH 256

__device__ float g_bufA[(size_t)MAXN * 128]; // ping (up to N x 128)
__device__ float g_bufB[(size_t)MAXN * 64];  // pong (N x 64)
__device__ float g_xagg[(size_t)MAXN * 5];   // aggregated input features
__device__ int   g_cnt[MAXN];
__device__ int   g_rowptr[MAXN + 1];
__device__ int   g_curoff[MAXN];
__device__ float g_dinv[MAXN];
__device__ int   g_col[MAXE];
__device__ float g_wgt[MAXE];
__device__ int   g_bsums[1024];
__device__ float g_pool[NGRAPH * 64];
__device__ float g_gcnt[NGRAPH];
__device__ int   g_is64[1];   // 1 if index arrays are int64, 0 if int32

// dtype-robust index load
__device__ __forceinline__ int load_idx(const void* p, long long i, int is64) {
    if (is64) return (int)((const long long*)p)[i];
    return ((const int*)p)[i];
}

// ---------------- dtype detection ----------------
// View edge buffer as int32 pairs. int64 values < 2^32 have zero high words;
// int32 storage has random edge indices there. Reads 4KB (safe either way).
__global__ void k_detect(const int* __restrict__ p, int* flag) {
    __shared__ int any;
    if (threadIdx.x == 0) any = 0;
    __syncthreads();
    for (int i = threadIdx.x; i < 512; i += blockDim.x) {
        if (p[2 * i + 1] != 0) atomicOr(&any, 1);
    }
    __syncthreads();
    if (threadIdx.x == 0) flag[0] = any ? 0 : 1;
}

// ---------------- init ----------------
__global__ void k_init(int* cnt, float* pool, float* gcnt, int n) {
    int i = blockIdx.x * blockDim.x + threadIdx.x;
    if (i < n) cnt[i] = 0;
    if (i < NGRAPH * 64) pool[i] = 0.f;
    if (i < NGRAPH) gcnt[i] = 0.f;
}

// ---------------- degree count ----------------
__global__ void k_count(const void* __restrict__ ei, int E, int* cnt, const int* flag) {
    int is64 = flag[0];
    int e = blockIdx.x * blockDim.x + threadIdx.x;
    if (e < E) {
        int d = load_idx(ei, (long long)E + e, is64);
        atomicAdd(&cnt[d], 1);
    }
}

__global__ void k_dinv(const int* __restrict__ cnt, float* dinv, int n) {
    int i = blockIdx.x * blockDim.x + threadIdx.x;
    if (i < n) dinv[i] = rsqrtf((float)cnt[i] + 1.0f); // +1 self loop
}

// ---------------- exclusive scan (3 kernels) ----------------
__global__ void k_scan1(const int* __restrict__ cnt, int* rowptr, int* bsums, int n) {
    __shared__ int s[1024];
    int i = blockIdx.x * 1024 + threadIdx.x;
    int v = (i < n) ? cnt[i] : 0;
    s[threadIdx.x] = v;
    __syncthreads();
    for (int off = 1; off < 1024; off <<= 1) {
        int t = 0;
        if ((int)threadIdx.x >= off) t = s[threadIdx.x - off];
        __syncthreads();
        s[threadIdx.x] += t;
        __syncthreads();
    }
    if (i < n) rowptr[i] = s[threadIdx.x] - v; // exclusive within block
    if (threadIdx.x == 1023) bsums[blockIdx.x] = s[1023];
}

__global__ void k_scan2(int* bsums, int nb) {
    if (threadIdx.x == 0 && blockIdx.x == 0) {
        int acc = 0;
        for (int b = 0; b < nb; b++) { int t = bsums[b]; bsums[b] = acc; acc += t; }
    }
}

__global__ void k_scan3(int* rowptr, int* curoff, const int* __restrict__ bsums, int n, int E) {
    int i = blockIdx.x * blockDim.x + threadIdx.x;
    if (i < n) {
        int r = rowptr[i] + bsums[i >> 10];
        rowptr[i] = r;
        curoff[i] = r;
    }
    if (i == 0) rowptr[n] = E;
}

// ---------------- CSR fill ----------------
__global__ void k_fill(const void* __restrict__ ei, int E,
                       const float* __restrict__ dinv,
                       int* curoff, int* col, float* wgt, const int* flag) {
    int is64 = flag[0];
    int e = blockIdx.x * blockDim.x + threadIdx.x;
    if (e >= E) return;
    int s = load_idx(ei, e, is64);
    int d = load_idx(ei, (long long)E + e, is64);
    int p = atomicAdd(&curoff[d], 1);
    col[p] = s;
    wgt[p] = dinv[s] * dinv[d];
}

// ---------------- aggregation, width 5 (8 lanes per node) ----------------
__global__ void k_agg5(const float* __restrict__ x,
                       const int* __restrict__ rowptr, const int* __restrict__ col,
                       const float* __restrict__ wgt, const float* __restrict__ dinv,
                       float* __restrict__ out, int n) {
    int t = blockIdx.x * blockDim.x + threadIdx.x;
    int node = t >> 3;
    int f = t & 7;
    if (node >= n) return;
    int beg = rowptr[node], end = rowptr[node + 1];
    bool valid = (f < 5);
    float acc = 0.f;
    for (int e = beg; e < end; e++) {
        int s = col[e];
        float w = wgt[e];
        if (valid) acc += w * __ldg(&x[(size_t)s * 5 + f]);
    }
    float ds = dinv[node];
    if (valid) {
        acc += ds * ds * x[(size_t)node * 5 + f];
        out[(size_t)node * 5 + f] = acc;
    }
}

// ---------------- aggregation, width 64 (warp per node) ----------------
template <bool RELU>
__global__ void k_agg64(const float* __restrict__ h,
                        const int* __restrict__ rowptr, const int* __restrict__ col,
                        const float* __restrict__ wgt, const float* __restrict__ dinv,
                        const float* __restrict__ bias,
                        float* __restrict__ out, int n) {
    int node = blockIdx.x * 8 + (threadIdx.x >> 5);
    int lane = threadIdx.x & 31;
    if (node >= n) return;
    int beg = rowptr[node], end = rowptr[node + 1];
    float a0 = 0.f, a1 = 0.f;
    int e = beg;
    for (; e + 1 < end; e += 2) {
        int s0 = col[e], s1 = col[e + 1];
        float w0 = wgt[e], w1 = wgt[e + 1];
        const float* p0 = h + (size_t)s0 * 64;
        const float* p1 = h + (size_t)s1 * 64;
        a0 += w0 * __ldg(&p0[lane])      + w1 * __ldg(&p1[lane]);
        a1 += w0 * __ldg(&p0[lane + 32]) + w1 * __ldg(&p1[lane + 32]);
    }
    if (e < end) {
        int s = col[e];
        float w = wgt[e];
        a0 += w * __ldg(&h[(size_t)s * 64 + lane]);
        a1 += w * __ldg(&h[(size_t)s * 64 + lane + 32]);
    }
    float ds = dinv[node];
    float ws = ds * ds;
    a0 += ws * h[(size_t)node * 64 + lane];
    a1 += ws * h[(size_t)node * 64 + lane + 32];
    if (RELU) {
        a0 = fmaxf(a0 + __ldg(&bias[lane]), 0.f);
        a1 = fmaxf(a1 + __ldg(&bias[lane + 32]), 0.f);
    }
    out[(size_t)node * 64 + lane]      = a0;
    out[(size_t)node * 64 + lane + 32] = a1;
}

// ---------------- GEMM layer 1: (N x 5) @ (5 x 64) + b, relu ----------------
__global__ void k_gemm1(const float* __restrict__ a, const float* __restrict__ W,
                        const float* __restrict__ b, float* __restrict__ out, int n) {
    __shared__ float Ws[5 * 64];
    __shared__ float bs[64];
    int t = threadIdx.x;
    for (int i = t; i < 5 * 64; i += 256) Ws[i] = W[i];
    if (t < 64) bs[t] = b[t];
    __syncthreads();
    int node = blockIdx.x * 8 + (t >> 5);
    int lane = t & 31;
    if (node >= n) return;
    float xr[5];
#pragma unroll
    for (int k = 0; k < 5; k++) xr[k] = a[(size_t)node * 5 + k];
#pragma unroll
    for (int c = 0; c < 2; c++) {
        int j = lane + c * 32;
        float acc = bs[j];
#pragma unroll
        for (int k = 0; k < 5; k++) acc += xr[k] * Ws[k * 64 + j];
        out[(size_t)node * 64 + j] = fmaxf(acc, 0.f);
    }
}

// ---------------- tiled fp32 GEMM: 64-node tile x NC cols ----------------
// thread layout: 16 col-groups x 16 node-groups, microtile 4 nodes x MC cols
template <int K, int NC, int MC, bool RELU>
__launch_bounds__(256)
__global__ void k_gemm(const float* __restrict__ A, const float* __restrict__ W,
                       const float* __restrict__ bias, float* __restrict__ out, int n) {
    constexpr int KC = 64;
    __shared__ float As[KC][64];  // transposed: As[k][node]
    __shared__ float Bs[KC][NC];
    const int t = threadIdx.x;
    const int tx = t & 15;   // col group  -> cols [tx*MC, tx*MC+MC)
    const int ty = t >> 4;   // node group -> nodes [ty*4, ty*4+4)
    const int nodeBase = blockIdx.x * 64;

    float acc[4][MC];
#pragma unroll
    for (int i = 0; i < 4; i++)
#pragma unroll
        for (int j = 0; j < MC; j++) acc[i][j] = 0.f;

    for (int k0 = 0; k0 < K; k0 += KC) {
        // load A chunk (64 nodes x KC) transposed into smem
        for (int q = t; q < 64 * KC / 4; q += 256) {
            int node = q >> 4;          // KC/4 == 16
            int kk4 = (q & 15) * 4;
            int gn = nodeBase + node;
            float4 v = make_float4(0.f, 0.f, 0.f, 0.f);
            if (gn < n)
                v = *reinterpret_cast<const float4*>(&A[(size_t)gn * K + k0 + kk4]);
            As[kk4 + 0][node] = v.x;
            As[kk4 + 1][node] = v.y;
            As[kk4 + 2][node] = v.z;
            As[kk4 + 3][node] = v.w;
        }
        // load B chunk (KC x NC)
        for (int q = t; q < KC * NC / 4; q += 256) {
            int kk = q / (NC / 4);
            int c4 = (q % (NC / 4)) * 4;
            *reinterpret_cast<float4*>(&Bs[kk][c4]) =
                *reinterpret_cast<const float4*>(&W[(size_t)(k0 + kk) * NC + c4]);
        }
        __syncthreads();
#pragma unroll
        for (int kk = 0; kk < KC; kk++) {
            float4 av = *reinterpret_cast<const float4*>(&As[kk][ty * 4]);
            float a4[4] = {av.x, av.y, av.z, av.w};
            float bv[MC];
#pragma unroll
            for (int j = 0; j < MC; j += 4) {
                float4 b4 = *reinterpret_cast<const float4*>(&Bs[kk][tx * MC + j]);
                bv[j] = b4.x; bv[j + 1] = b4.y; bv[j + 2] = b4.z; bv[j + 3] = b4.w;
            }
#pragma unroll
            for (int i = 0; i < 4; i++)
#pragma unroll
                for (int j = 0; j < MC; j++) acc[i][j] += a4[i] * bv[j];
        }
        __syncthreads();
    }
#pragma unroll
    for (int i = 0; i < 4; i++) {
        int gn = nodeBase + ty * 4 + i;
        if (gn < n) {
#pragma unroll
            for (int j = 0; j < MC; j++) {
                int c = tx * MC + j;
                float v = acc[i][j];
                if (RELU) v = fmaxf(v + __ldg(&bias[c]), 0.f);
                out[(size_t)gn * NC + c] = v;
            }
        }
    }
}

// ---------------- mean pool (atomic accumulate) ----------------
__global__ void k_pool(const float* __restrict__ h, const void* __restrict__ batch,
                       float* pool, float* gcnt, int n, const int* flag) {
    int is64 = flag[0];
    int t = blockIdx.x * blockDim.x + threadIdx.x;
    int node = t >> 6;
    int f = t & 63;
    if (node >= n) return;
    int g = load_idx(batch, node, is64);
    atomicAdd(&pool[g * 64 + f], h[(size_t)node * 64 + f]);
    if (f == 0) atomicAdd(&gcnt[g], 1.0f);
}

// ---------------- final FC + sigmoid ----------------
__global__ void k_final(const float* __restrict__ pool, const float* __restrict__ gcnt,
                        const float* __restrict__ Wfc, const float* __restrict__ bfc,
                        float* __restrict__ out) {
    int g = threadIdx.x;
    float c = fmaxf(gcnt[g], 1.0f);
    float acc = 0.f;
#pragma unroll
    for (int k = 0; k < 64; k++) acc += pool[g * 64 + k] * Wfc[k];
    acc = acc / c + bfc[0];
    out[g] = 1.f / (1.f + expf(-acc));
}

// ---------------- launch ----------------
extern "C" void kernel_launch(void* const* d_in, const int* in_sizes, int n_in,
                              void* d_out, int out_size) {
    const float*  x     = (const float*)d_in[0];
    const void*   ei    = d_in[1];
    const void*   batch = d_in[2];
    const float*  W1    = (const float*)d_in[3];
    const float*  b1    = (const float*)d_in[4];
    const float*  W2    = (const float*)d_in[5];
    const float*  b2    = (const float*)d_in[6];
    const float*  W3    = (const float*)d_in[7];
    const float*  b3    = (const float*)d_in[8];
    const float*  Wfc   = (const float*)d_in[9];
    const float*  bfc   = (const float*)d_in[10];
    float*        out   = (float*)d_out;

    const int N = in_sizes[0] / 5;
    const int E = in_sizes[1] / 2;

    // resolve device-global scratch addresses
    float *bufA, *bufB, *xagg, *dinv, *wgt, *pool, *gcnt;
    int *cnt, *rowptr, *curoff, *col, *bsums, *is64;
    cudaGetSymbolAddress((void**)&bufA, g_bufA);
    cudaGetSymbolAddress((void**)&bufB, g_bufB);
    cudaGetSymbolAddress((void**)&xagg, g_xagg);
    cudaGetSymbolAddress((void**)&dinv, g_dinv);
    cudaGetSymbolAddress((void**)&wgt, g_wgt);
    cudaGetSymbolAddress((void**)&pool, g_pool);
    cudaGetSymbolAddress((void**)&gcnt, g_gcnt);
    cudaGetSymbolAddress((void**)&cnt, g_cnt);
    cudaGetSymbolAddress((void**)&rowptr, g_rowptr);
    cudaGetSymbolAddress((void**)&curoff, g_curoff);
    cudaGetSymbolAddress((void**)&col, g_col);
    cudaGetSymbolAddress((void**)&bsums, g_bsums);
    cudaGetSymbolAddress((void**)&is64, g_is64);

    const int TB = 256;

    k_detect<<<1, 256>>>((const int*)ei, is64);

    int initN = N > NGRAPH * 64 ? N : NGRAPH * 64;
    k_init<<<(initN + TB - 1) / TB, TB>>>(cnt, pool, gcnt, N);

    k_count<<<(E + TB - 1) / TB, TB>>>(ei, E, cnt, is64);
    k_dinv<<<(N + TB - 1) / TB, TB>>>(cnt, dinv, N);

    int nb = (N + 1023) / 1024;
    k_scan1<<<nb, 1024>>>(cnt, rowptr, bsums, N);
    k_scan2<<<1, 32>>>(bsums, nb);
    k_scan3<<<(N + TB - 1) / TB, TB>>>(rowptr, curoff, bsums, N, E);
    k_fill<<<(E + TB - 1) / TB, TB>>>(ei, E, dinv, curoff, col, wgt, is64);

    // Layer 1: aggregate x (width 5), then (5->64) GEMM + bias + relu
    k_agg5<<<(N * 8 + TB - 1) / TB, TB>>>(x, rowptr, col, wgt, dinv, xagg, N);
    k_gemm1<<<(N + 7) / 8, TB>>>(xagg, W1, b1, bufA, N);

    // Layer 2: aggregate (width 64), then (64->128) GEMM + bias + relu
    k_agg64<false><<<(N + 7) / 8, TB>>>(bufA, rowptr, col, wgt, dinv, nullptr, bufB, N);
    k_gemm<64, 128, 8, true><<<(N + 63) / 64, TB>>>(bufB, W2, b2, bufA, N);

    // Layer 3: (128->64) GEMM, then aggregate + bias + relu
    k_gemm<128, 64, 4, false><<<(N + 63) / 64, TB>>>(bufA, W3, nullptr, bufB, N);
    k_agg64<true><<<(N + 7) / 8, TB>>>(bufB, rowptr, col, wgt, dinv, b3, bufA, N);

    // Pool + final
    k_pool<<<((size_t)N * 64 + TB - 1) / TB, TB>>>(bufA, batch, pool, gcnt, N, is64);
    k_final<<<1, NGRAPH>>>(pool, gcnt, Wfc, bfc, out);
}

// round 3
// speedup vs baseline: 1.0561x; 1.0561x over previous
#include <cuda_runtime.h>
#include <cuda_bf16.h>
#include <math.h>

// ---------------- static scratch (no allocations allowed) ----------------
#define MAXN 100000
#define MAXE 1600000
#define NGRAPH 256

__device__ float g_bufA[(size_t)MAXN * 128]; // ping (up to N x 128)
__device__ float g_bufB[(size_t)MAXN * 64];  // pong (N x 64)
__device__ int   g_cnt[MAXN];
__device__ int   g_rowptr[MAXN + 1];
__device__ int   g_curoff[MAXN];
__device__ float g_dinv[MAXN];
__device__ int   g_col[MAXE];
__device__ float g_wgt[MAXE];
__device__ int   g_bsums[1024];
__device__ float g_pool[NGRAPH * 64];
__device__ float g_gcnt[NGRAPH];
__device__ int   g_is64[1];   // 1 if index arrays are int64, 0 if int32

// dtype-robust index load
__device__ __forceinline__ int load_idx(const void* p, long long i, int is64) {
    if (is64) return (int)((const long long*)p)[i];
    return ((const int*)p)[i];
}

// ---------------- init (+ dtype detect in block 0) ----------------
// Detect: view edge buffer as int32 pairs. int64 values < 2^32 have zero high
// words; int32 storage has random edge indices there. Reads 4KB (safe both ways).
__global__ void k_init(int* cnt, float* pool, float* gcnt, int n,
                       const int* __restrict__ eprobe, int* flag) {
    int i = blockIdx.x * blockDim.x + threadIdx.x;
    if (i < n) cnt[i] = 0;
    if (i < NGRAPH * 64) pool[i] = 0.f;
    if (i < NGRAPH) gcnt[i] = 0.f;
    if (blockIdx.x == 0) {
        __shared__ int any;
        if (threadIdx.x == 0) any = 0;
        __syncthreads();
        int loc = 0;
        for (int q = threadIdx.x; q < 512; q += blockDim.x)
            if (eprobe[2 * q + 1] != 0) loc = 1;
        if (loc) atomicOr(&any, 1);
        __syncthreads();
        if (threadIdx.x == 0) flag[0] = any ? 0 : 1;
    }
}

// ---------------- degree count ----------------
__global__ void k_count(const void* __restrict__ ei, int E, int* cnt, const int* flag) {
    int is64 = flag[0];
    int e = blockIdx.x * blockDim.x + threadIdx.x;
    if (e < E) {
        int d = load_idx(ei, (long long)E + e, is64);
        atomicAdd(&cnt[d], 1);
    }
}

// ---------------- exclusive scan (3 kernels) ----------------
__global__ void k_scan1(const int* __restrict__ cnt, int* rowptr, int* bsums, int n) {
    __shared__ int s[1024];
    int i = blockIdx.x * 1024 + threadIdx.x;
    int v = (i < n) ? cnt[i] : 0;
    s[threadIdx.x] = v;
    __syncthreads();
    for (int off = 1; off < 1024; off <<= 1) {
        int t = 0;
        if ((int)threadIdx.x >= off) t = s[threadIdx.x - off];
        __syncthreads();
        s[threadIdx.x] += t;
        __syncthreads();
    }
    if (i < n) rowptr[i] = s[threadIdx.x] - v; // exclusive within block
    if (threadIdx.x == 1023) bsums[blockIdx.x] = s[1023];
}

__global__ void k_scan2(int* bsums, int nb) {
    if (threadIdx.x == 0 && blockIdx.x == 0) {
        int acc = 0;
        for (int b = 0; b < nb; b++) { int t = bsums[b]; bsums[b] = acc; acc += t; }
    }
}

// scan finalize + dinv (fused)
__global__ void k_scan3(int* rowptr, int* curoff, const int* __restrict__ bsums,
                        const int* __restrict__ cnt, float* dinv, int n, int E) {
    int i = blockIdx.x * blockDim.x + threadIdx.x;
    if (i < n) {
        int r = rowptr[i] + bsums[i >> 10];
        rowptr[i] = r;
        curoff[i] = r;
        dinv[i] = rsqrtf((float)cnt[i] + 1.0f); // +1 self loop
    }
    if (i == 0) rowptr[n] = E;
}

// ---------------- CSR fill ----------------
__global__ void k_fill(const void* __restrict__ ei, int E,
                       const float* __restrict__ dinv,
                       int* curoff, int* col, float* wgt, const int* flag) {
    int is64 = flag[0];
    int e = blockIdx.x * blockDim.x + threadIdx.x;
    if (e >= E) return;
    int s = load_idx(ei, e, is64);
    int d = load_idx(ei, (long long)E + e, is64);
    int p = atomicAdd(&curoff[d], 1);
    col[p] = s;
    wgt[p] = dinv[s] * dinv[d];
}

// ---------------- fused layer1: agg(x) (width 5) + GEMM(5->64) + relu --------
// 8 lanes per node. Lanes 0..4 aggregate one feature each; after shuffle
// broadcast, each lane computes 8 output columns.
__global__ void k_l1(const float* __restrict__ x,
                     const int* __restrict__ rowptr, const int* __restrict__ col,
                     const float* __restrict__ wgt, const float* __restrict__ dinv,
                     const float* __restrict__ W1, const float* __restrict__ b1,
                     float* __restrict__ out, int n) {
    __shared__ float Ws[5 * 64];
    __shared__ float bs[64];
    int t = threadIdx.x;
    for (int i = t; i < 5 * 64; i += 256) Ws[i] = W1[i];
    if (t < 64) bs[t] = b1[t];
    __syncthreads();

    int gt = blockIdx.x * 256 + t;
    int node = gt >> 3;
    int f = gt & 7;
    bool live = (node < n);
    int nodec = live ? node : (n - 1);   // clamp so no lane exits (shuffle safety)

    int beg = rowptr[nodec], end = rowptr[nodec + 1];
    bool valid = (f < 5);
    float acc = 0.f;
    for (int e = beg; e < end; e++) {
        int s = col[e];
        float w = wgt[e];
        if (valid) acc += w * __ldg(&x[(size_t)s * 5 + f]);
    }
    float ds = dinv[nodec];
    if (valid) acc += ds * ds * x[(size_t)nodec * 5 + f];

    float v[5];
#pragma unroll
    for (int k = 0; k < 5; k++) v[k] = __shfl_sync(0xffffffffu, acc, k, 8);

    int cb = f * 8;
    float o[8];
#pragma unroll
    for (int j = 0; j < 8; j++) {
        float a = bs[cb + j];
#pragma unroll
        for (int k = 0; k < 5; k++) a += v[k] * Ws[k * 64 + cb + j];
        o[j] = fmaxf(a, 0.f);
    }
    if (live) {
        float4* p = reinterpret_cast<float4*>(&out[(size_t)node * 64 + cb]);
        p[0] = make_float4(o[0], o[1], o[2], o[3]);
        p[1] = make_float4(o[4], o[5], o[6], o[7]);
    }
}

// ---------------- aggregation, width 64 (warp per node, 4-edge unroll) -------
// POOL=false: plain write to out. POOL=true: +bias, relu, atomic mean-pool.
template <bool POOL>
__global__ void k_agg64(const float* __restrict__ h,
                        const int* __restrict__ rowptr, const int* __restrict__ col,
                        const float* __restrict__ wgt, const float* __restrict__ dinv,
                        const float* __restrict__ bias,
                        const void* __restrict__ batch, const int* flag,
                        float* __restrict__ out, float* pool, float* gcnt, int n) {
    int node = blockIdx.x * 8 + (threadIdx.x >> 5);
    int lane = threadIdx.x & 31;
    if (node >= n) return;
    int beg = rowptr[node], end = rowptr[node + 1];
    float a0 = 0.f, a1 = 0.f;
    int e = beg;
    for (; e + 3 < end; e += 4) {
        int s0 = col[e], s1 = col[e + 1], s2 = col[e + 2], s3 = col[e + 3];
        float w0 = wgt[e], w1 = wgt[e + 1], w2 = wgt[e + 2], w3 = wgt[e + 3];
        const float* p0 = h + (size_t)s0 * 64;
        const float* p1 = h + (size_t)s1 * 64;
        const float* p2 = h + (size_t)s2 * 64;
        const float* p3 = h + (size_t)s3 * 64;
        float x00 = __ldg(p0 + lane),      x01 = __ldg(p0 + lane + 32);
        float x10 = __ldg(p1 + lane),      x11 = __ldg(p1 + lane + 32);
        float x20 = __ldg(p2 + lane),      x21 = __ldg(p2 + lane + 32);
        float x30 = __ldg(p3 + lane),      x31 = __ldg(p3 + lane + 32);
        a0 += w0 * x00 + w1 * x10 + w2 * x20 + w3 * x30;
        a1 += w0 * x01 + w1 * x11 + w2 * x21 + w3 * x31;
    }
    for (; e < end; e++) {
        int s = col[e];
        float w = wgt[e];
        a0 += w * __ldg(&h[(size_t)s * 64 + lane]);
        a1 += w * __ldg(&h[(size_t)s * 64 + lane + 32]);
    }
    float ds = dinv[node];
    float ws = ds * ds;
    a0 += ws * h[(size_t)node * 64 + lane];
    a1 += ws * h[(size_t)node * 64 + lane + 32];
    if (POOL) {
        a0 = fmaxf(a0 + __ldg(&bias[lane]), 0.f);
        a1 = fmaxf(a1 + __ldg(&bias[lane + 32]), 0.f);
        int g = load_idx(batch, node, flag[0]);
        atomicAdd(&pool[g * 64 + lane], a0);
        atomicAdd(&pool[g * 64 + lane + 32], a1);
        if (lane == 0) atomicAdd(&gcnt[g], 1.0f);
    } else {
        out[(size_t)node * 64 + lane]      = a0;
        out[(size_t)node * 64 + lane + 32] = a1;
    }
}

// ---------------- tiled fp32 GEMM: 64-node tile x NC cols ----------------
// thread layout: 16 col-groups x 16 node-groups, microtile 4 nodes x MC cols
template <int K, int NC, int MC, bool RELU>
__launch_bounds__(256)
__global__ void k_gemm(const float* __restrict__ A, const float* __restrict__ W,
                       const float* __restrict__ bias, float* __restrict__ out, int n) {
    constexpr int KC = 64;
    __shared__ float As[KC][64];  // transposed: As[k][node]
    __shared__ float Bs[KC][NC];
    const int t = threadIdx.x;
    const int tx = t & 15;   // col group  -> cols [tx*MC, tx*MC+MC)
    const int ty = t >> 4;   // node group -> nodes [ty*4, ty*4+4)
    const int nodeBase = blockIdx.x * 64;

    float acc[4][MC];
#pragma unroll
    for (int i = 0; i < 4; i++)
#pragma unroll
        for (int j = 0; j < MC; j++) acc[i][j] = 0.f;

    for (int k0 = 0; k0 < K; k0 += KC) {
        for (int q = t; q < 64 * KC / 4; q += 256) {
            int node = q >> 4;          // KC/4 == 16
            int kk4 = (q & 15) * 4;
            int gn = nodeBase + node;
            float4 v = make_float4(0.f, 0.f, 0.f, 0.f);
            if (gn < n)
                v = *reinterpret_cast<const float4*>(&A[(size_t)gn * K + k0 + kk4]);
            As[kk4 + 0][node] = v.x;
            As[kk4 + 1][node] = v.y;
            As[kk4 + 2][node] = v.z;
            As[kk4 + 3][node] = v.w;
        }
        for (int q = t; q < KC * NC / 4; q += 256) {
            int kk = q / (NC / 4);
            int c4 = (q % (NC / 4)) * 4;
            *reinterpret_cast<float4*>(&Bs[kk][c4]) =
                *reinterpret_cast<const float4*>(&W[(size_t)(k0 + kk) * NC + c4]);
        }
        __syncthreads();
#pragma unroll
        for (int kk = 0; kk < KC; kk++) {
            float4 av = *reinterpret_cast<const float4*>(&As[kk][ty * 4]);
            float a4[4] = {av.x, av.y, av.z, av.w};
            float bv[MC];
#pragma unroll
            for (int j = 0; j < MC; j += 4) {
                float4 b4 = *reinterpret_cast<const float4*>(&Bs[kk][tx * MC + j]);
                bv[j] = b4.x; bv[j + 1] = b4.y; bv[j + 2] = b4.z; bv[j + 3] = b4.w;
            }
#pragma unroll
            for (int i = 0; i < 4; i++)
#pragma unroll
                for (int j = 0; j < MC; j++) acc[i][j] += a4[i] * bv[j];
        }
        __syncthreads();
    }
#pragma unroll
    for (int i = 0; i < 4; i++) {
        int gn = nodeBase + ty * 4 + i;
        if (gn < n) {
#pragma unroll
            for (int j = 0; j < MC; j++) {
                int c = tx * MC + j;
                float v = acc[i][j];
                if (RELU) v = fmaxf(v + __ldg(&bias[c]), 0.f);
                out[(size_t)gn * NC + c] = v;
            }
        }
    }
}

// ---------------- final FC + sigmoid ----------------
__global__ void k_final(const float* __restrict__ pool, const float* __restrict__ gcnt,
                        const float* __restrict__ Wfc, const float* __restrict__ bfc,
                        float* __restrict__ out) {
    int g = threadIdx.x;
    float c = fmaxf(gcnt[g], 1.0f);
    float acc = 0.f;
#pragma unroll
    for (int k = 0; k < 64; k++) acc += pool[g * 64 + k] * Wfc[k];
    acc = acc / c + bfc[0];
    out[g] = 1.f / (1.f + expf(-acc));
}

// ---------------- launch ----------------
extern "C" void kernel_launch(void* const* d_in, const int* in_sizes, int n_in,
                              void* d_out, int out_size) {
    const float*  x     = (const float*)d_in[0];
    const void*   ei    = d_in[1];
    const void*   batch = d_in[2];
    const float*  W1    = (const float*)d_in[3];
    const float*  b1    = (const float*)d_in[4];
    const float*  W2    = (const float*)d_in[5];
    const float*  b2    = (const float*)d_in[6];
    const float*  W3    = (const float*)d_in[7];
    const float*  b3    = (const float*)d_in[8];
    const float*  Wfc   = (const float*)d_in[9];
    const float*  bfc   = (const float*)d_in[10];
    float*        out   = (float*)d_out;

    const int N = in_sizes[0] / 5;
    const int E = in_sizes[1] / 2;

    float *bufA, *bufB, *dinv, *wgt, *pool, *gcnt;
    int *cnt, *rowptr, *curoff, *col, *bsums, *is64;
    cudaGetSymbolAddress((void**)&bufA, g_bufA);
    cudaGetSymbolAddress((void**)&bufB, g_bufB);
    cudaGetSymbolAddress((void**)&dinv, g_dinv);
    cudaGetSymbolAddress((void**)&wgt, g_wgt);
    cudaGetSymbolAddress((void**)&pool, g_pool);
    cudaGetSymbolAddress((void**)&gcnt, g_gcnt);
    cudaGetSymbolAddress((void**)&cnt, g_cnt);
    cudaGetSymbolAddress((void**)&rowptr, g_rowptr);
    cudaGetSymbolAddress((void**)&curoff, g_curoff);
    cudaGetSymbolAddress((void**)&col, g_col);
    cudaGetSymbolAddress((void**)&bsums, g_bsums);
    cudaGetSymbolAddress((void**)&is64, g_is64);

    const int TB = 256;
    int initN = N > NGRAPH * 64 ? N : NGRAPH * 64;
    k_init<<<(initN + TB - 1) / TB, TB>>>(cnt, pool, gcnt, N, (const int*)ei, is64);

    k_count<<<(E + TB - 1) / TB, TB>>>(ei, E, cnt, is64);

    int nb = (N + 1023) / 1024;
    k_scan1<<<nb, 1024>>>(cnt, rowptr, bsums, N);
    k_scan2<<<1, 32>>>(bsums, nb);
    k_scan3<<<(N + TB - 1) / TB, TB>>>(rowptr, curoff, bsums, cnt, dinv, N, E);
    k_fill<<<(E + TB - 1) / TB, TB>>>(ei, E, dinv, curoff, col, wgt, is64);

    // Layer 1 fused: agg5 + (5->64) GEMM + bias + relu  -> bufA
    k_l1<<<(N * 8 + TB - 1) / TB, TB>>>(x, rowptr, col, wgt, dinv, W1, b1, bufA, N);

    // Layer 2: aggregate (width 64) -> bufB, then (64->128) GEMM + relu -> bufA
    k_agg64<false><<<(N + 7) / 8, TB>>>(bufA, rowptr, col, wgt, dinv, nullptr,
                                        nullptr, is64, bufB, nullptr, nullptr, N);
    k_gemm<64, 128, 8, true><<<(N + 63) / 64, TB>>>(bufB, W2, b2, bufA, N);

    // Layer 3: (128->64) GEMM -> bufB, then aggregate + bias + relu + pool (fused)
    k_gemm<128, 64, 4, false><<<(N + 63) / 64, TB>>>(bufA, W3, nullptr, bufB, N);
    k_agg64<true><<<(N + 7) / 8, TB>>>(bufB, rowptr, col, wgt, dinv, b3,
                                       batch, is64, nullptr, pool, gcnt, N);

    k_final<<<1, NGRAPH>>>(pool, gcnt, Wfc, bfc, out);
}